// round 14
// baseline (speedup 1.0000x reference)
#include <cuda_runtime.h>
#include <cstdint>
#include <cstddef>

using ull = unsigned long long;

#define NROWS   16                     // rows per CTA
#define THREADS 128
// x row stride: 64*D + 4 floats  (== 4 mod 32: warp rows spread bank quads)
#define XSLOT   5184                   // floats: 16 * (64*5+4) worst case (l=2)
#define NSLOTS  3
#define SMEM_BYTES (NSLOTS * XSLOT * 4)   // 62208 B -> 3 CTAs/SM

__device__ __forceinline__ void cpa16(float* dst, const float* src) {
    unsigned d = (unsigned)__cvta_generic_to_shared(dst);
    asm volatile("cp.async.cg.shared.global [%0], [%1], 16;" :: "r"(d), "l"(src));
}
__device__ __forceinline__ ull pack2(float a) {
    ull r; asm("mov.b64 %0, {%1, %1};" : "=l"(r) : "f"(a)); return r;
}
__device__ __forceinline__ void ffma2(ull& acc, ull a, ull b) {
    asm("fma.rn.f32x2 %0, %1, %2, %0;" : "+l"(acc) : "l"(a), "l"(b));
}
__device__ __forceinline__ ull addf2(ull a, ull b) {
    ull r; asm("add.rn.f32x2 %0, %1, %2;" : "=l"(r) : "l"(a), "l"(b)); return r;
}

// Stage the x part of one (l, c) chunk into a ring slot (no commit).
template<int D>
__device__ __forceinline__ void stage_x(const float* __restrict__ x,
                                        int n0, int c, int off,
                                        float* xs, int tid)
{
    const int stride = 64 * D + 4;
    const int row = tid >> 3, l8 = tid & 7;   // 16 rows, 8 threads/row
    const float* gr = x + (size_t)(n0 + row) * 9216 + c * 576 + off;
    float* sr = xs + row * stride;
#pragma unroll
    for (int k = 0; k < 2 * D; k++) {
        int v4 = (l8 + 8 * k) * 4;
        cpa16(sr + v4, gr + v4);
    }
}

// Compute one chunk. D = irrep dim (1/3/5), DOFF = dim offset in acc (0/1/4).
// Thread (r, kg, og) owns mi in [kg*16, kg*16+16), outputs [og*8, og*8+8).
// x comes from smem; w rows come straight from gmem via __ldg (L1/L2-resident:
// every CTA reads the same 192 KB of weights).
template<int D, int DOFF>
__device__ __forceinline__ void compute_chunk(const float* __restrict__ xs,
                                              const float* __restrict__ wb,
                                              ull (&acc)[4][9], int r, int kg)
{
    const float* xr = xs + r * (64 * D + 4) + kg * (16 * D);
#pragma unroll
    for (int b = 0; b < 4; b++) {                    // blocks of 4 multiplicities
        float xh[4 * D];
        const float4* xp = (const float4*)(xr + b * 4 * D);
#pragma unroll
        for (int v = 0; v < D; v++) {
            float4 t = xp[v];
            xh[4*v] = t.x; xh[4*v+1] = t.y; xh[4*v+2] = t.z; xh[4*v+3] = t.w;
        }
#pragma unroll
        for (int u4 = 0; u4 < 4; u4++) {
            const int u = b * 4 + u4;                // local mi 0..15
            const ulonglong2* wp = (const ulonglong2*)(wb + u * 16);
            ulonglong2 w01 = __ldg(wp);              // 2x LDG.128 (L1-hot)
            ulonglong2 w23 = __ldg(wp + 1);
            ull w4r[4] = { w01.x, w01.y, w23.x, w23.y };
#pragma unroll
            for (int d = 0; d < D; d++) {
                ull av = pack2(xh[u4 * D + d]);      // 1 pack feeds 4 FFMA2
#pragma unroll
                for (int p = 0; p < 4; p++)
                    ffma2(acc[p][DOFF + d], av, w4r[p]);
            }
        }
    }
}

__global__ void __launch_bounds__(THREADS, 3)
GeneralLinear_841813590622_kernel(const float* __restrict__ x,
                                  const float* __restrict__ w0,
                                  const float* __restrict__ w1,
                                  const float* __restrict__ w2,
                                  float* __restrict__ out)
{
    extern __shared__ float smem[];
    const float* wl[3] = { w0, w1, w2 };

    const int tid = threadIdx.x;
    const int n0 = blockIdx.x * NROWS;
    const int r = tid >> 3, kg = (tid >> 1) & 3, og = tid & 1;
    const int wofs = kg * 256 + og * 8;   // + c*1024 + u*16 selects the w row slice

    ull acc[4][9];
#pragma unroll
    for (int p = 0; p < 4; p++)
#pragma unroll
        for (int q = 0; q < 9; q++) acc[p][q] = 0ull;

    // prologue: stage chunks 0 and 1 (both l=0) into slots 0 and 1
    stage_x<1>(x, n0, 0, 0, smem, tid);
    asm volatile("cp.async.commit_group;" ::: "memory");
    stage_x<1>(x, n0, 1, 0, smem + XSLOT, tid);
    asm volatile("cp.async.commit_group;" ::: "memory");

    for (int i = 0; i < 48; i++) {
        // my chunk-i copies landed (latest commit is chunk i+1 => keep 1 pending)
        asm volatile("cp.async.wait_group 1;" ::: "memory");
        // everyone's chunk-i copies landed (each thread waited before arriving),
        // and all compute of chunk i-1 is done -> slot (i+2)%3 is free.
        __syncthreads();

        const int nx = i + 2;
        if (nx < 48) {
            const int ln = nx >> 4, cn = nx & 15;
            float* xsn = smem + (size_t)(nx % 3) * XSLOT;
            if (ln == 0)      stage_x<1>(x, n0, cn, 0,   xsn, tid);
            else if (ln == 1) stage_x<3>(x, n0, cn, 64,  xsn, tid);
            else              stage_x<5>(x, n0, cn, 256, xsn, tid);
        }
        asm volatile("cp.async.commit_group;" ::: "memory");

        const int l = i >> 4, c = i & 15;
        const float* xsb = smem + (size_t)(i % 3) * XSLOT;
        const float* wb = wl[l] + c * 1024 + wofs;
        if (l == 0)      compute_chunk<1, 0>(xsb, wb, acc, r, kg);
        else if (l == 1) compute_chunk<3, 1>(xsb, wb, acc, r, kg);
        else             compute_chunk<5, 4>(xsb, wb, acc, r, kg);
    }

    // ---- reduce over kg (lane bits 1..2) via 64-bit butterfly shuffles ----
#pragma unroll
    for (int mask = 2; mask <= 4; mask <<= 1) {
#pragma unroll
        for (int p = 0; p < 4; p++)
#pragma unroll
            for (int q = 0; q < 9; q++) {
                ull o = __shfl_xor_sync(0xffffffffu, acc[p][q], mask);
                acc[p][q] = addf2(acc[p][q], o);
            }
    }

    // ---- kg==0 threads stage their (row, og-half) 72 floats to smem ----
    // slot 0 is safe: chunk 45 (slot 0) was consumed before the i=46 barrier;
    // laggard warps are in chunks 46/47 (slots 1/2).
    const float s = 0.03125f;   // 1/sqrt(1024)
    float* sred = smem;
    if ((tid & 6) == 0) {       // kg == 0
#pragma unroll
        for (int p = 0; p < 4; p++)
#pragma unroll
            for (int q = 0; q < 9; q++) {
                float lo, hi;
                asm("mov.b64 {%0, %1}, %2;" : "=f"(lo), "=f"(hi) : "l"(acc[p][q]));
                sred[r * 144 + (og * 8 + 2 * p) * 9 + q]     = lo * s;
                sred[r * 144 + (og * 8 + 2 * p + 1) * 9 + q] = hi * s;
            }
    }
    __syncthreads();

    // ---- cooperative coalesced float4 store: 16 rows * 144 floats = 576 float4 ----
    const float4* s4 = (const float4*)sred;
    float4* o4 = (float4*)(out + (size_t)n0 * 144);
#pragma unroll
    for (int k = 0; k < 5; k++) {
        int idx = tid + THREADS * k;
        if (idx < 576) o4[idx] = s4[idx];
    }
}

extern "C" void kernel_launch(void* const* d_in, const int* in_sizes, int n_in,
                              void* d_out, int out_size)
{
    const float* x  = (const float*)d_in[0];
    const float* w0 = (const float*)d_in[1];
    const float* w1 = (const float*)d_in[2];
    const float* w2 = (const float*)d_in[3];
    float* out = (float*)d_out;

    cudaFuncSetAttribute(GeneralLinear_841813590622_kernel,
                         cudaFuncAttributeMaxDynamicSharedMemorySize, SMEM_BYTES);
    GeneralLinear_841813590622_kernel<<<512, THREADS, SMEM_BYTES>>>(x, w0, w1, w2, out);
}

// round 15
// speedup vs baseline: 3.2525x; 3.2525x over previous
#include <cuda_runtime.h>
#include <cstdint>
#include <cstddef>

using ull = unsigned long long;

#define NROWS   16                     // rows per CTA
#define THREADS 128
// x row stride: 64*D + 4 floats  (== 4 mod 32: warp rows spread bank quads)
#define XS_BUF  5184                   // floats: 16 * (64*5+4) worst case (l=2)
#define WS_BUF  1280                   // floats: 64 w-rows * 20 (padded, permuted)
#define SLOT_FLOATS (XS_BUF + WS_BUF)  // 6464
#define NSLOTS  3
#define SMEM_BYTES (NSLOTS * SLOT_FLOATS * 4)   // 77568 B -> 3 CTAs/SM (232.7KB)

__device__ __forceinline__ void cpa16(float* dst, const float* src) {
    unsigned d = (unsigned)__cvta_generic_to_shared(dst);
    asm volatile("cp.async.cg.shared.global [%0], [%1], 16;" :: "r"(d), "l"(src));
}
__device__ __forceinline__ ull pack2(float a) {
    ull r; asm("mov.b64 %0, {%1, %1};" : "=l"(r) : "f"(a)); return r;
}
__device__ __forceinline__ void ffma2(ull& acc, ull a, ull b) {
    asm("fma.rn.f32x2 %0, %1, %2, %0;" : "+l"(acc) : "l"(a), "l"(b));
}
__device__ __forceinline__ ull addf2(ull a, ull b) {
    ull r; asm("add.rn.f32x2 %0, %1, %2;" : "=l"(r) : "l"(a), "l"(b)); return r;
}

// w smem row permutation (verified R8-R11): mi = kg*16 + uh*8 + ul ->
// pm = ul*8 + res, res = ((kg>>1)<<2) | (uh<<1) | (kg&1), row stride 20 floats.
// The 8 (kg,og) read addresses pm*20 + og*8 hit all 8 bank quads.
__device__ __forceinline__ int w_res(int kg, int uh) {
    return ((kg >> 1) << 2) | (uh << 1) | (kg & 1);
}

// Stage one (l, c) chunk (x rows + its 64x16 w slice) into a ring slot.
// One cp.async group per call (commit done by caller).
template<int D>
__device__ __forceinline__ void stage_chunk(const float* __restrict__ x,
                                            const float* __restrict__ wl,
                                            int n0, int c, int off,
                                            float* xs, float* ws, int tid)
{
    const int stride = 64 * D + 4;
    const int row = tid >> 3, l8 = tid & 7;   // 16 rows, 8 threads/row
    const float* gr = x + (size_t)(n0 + row) * 9216 + c * 576 + off;
    float* sr = xs + row * stride;
#pragma unroll
    for (int k = 0; k < 2 * D; k++) {
        int v4 = (l8 + 8 * k) * 4;
        cpa16(sr + v4, gr + v4);
    }
    // weights: w rows c*64..c*64+63, 256 float4 by 128 threads -> 2 each; permuted
    const int m = tid >> 1;                   // mi 0..63
    const int kg = m >> 4, uh = (m >> 3) & 1, ul = m & 7;
    const int pm = ul * 8 + w_res(kg, uh);
#pragma unroll
    for (int j = 0; j < 2; j++) {
        int q = (tid & 1) * 2 + j;            // float4 index within 16 floats
        cpa16(ws + pm * 20 + q * 4, wl + c * 1024 + m * 16 + q * 4);
    }
}

// Compute one chunk. D = irrep dim (1/3/5), DOFF = dim offset in acc (0/1/4).
// Thread (r, kg, og) owns mi in [kg*16, kg*16+16), outputs [og*8, og*8+8).
template<int D, int DOFF>
__device__ __forceinline__ void compute_chunk(const float* __restrict__ xs,
                                              const float* __restrict__ ws,
                                              ull (&acc)[4][9],
                                              int r, int kg, int og)
{
    const float* xr = xs + r * (64 * D + 4) + kg * (16 * D);
    const float* wbase = ws + og * 8;
#pragma unroll
    for (int b = 0; b < 4; b++) {                    // blocks of 4 multiplicities
        float xh[4 * D];
        const float4* xp = (const float4*)(xr + b * 4 * D);
#pragma unroll
        for (int v = 0; v < D; v++) {
            float4 t = xp[v];
            xh[4*v] = t.x; xh[4*v+1] = t.y; xh[4*v+2] = t.z; xh[4*v+3] = t.w;
        }
#pragma unroll
        for (int u4 = 0; u4 < 4; u4++) {
            const int u = b * 4 + u4;                // local mi 0..15
            const int uh = u >> 3, ul = u & 7;
            const int pm = ul * 8 + w_res(kg, uh);
            const ulonglong2* wp = (const ulonglong2*)(wbase + pm * 20);
            ulonglong2 w01 = wp[0], w23 = wp[1];     // 2x LDS.128, broadcast
            ull w4r[4] = { w01.x, w01.y, w23.x, w23.y };
#pragma unroll
            for (int d = 0; d < D; d++) {
                ull av = pack2(xh[u4 * D + d]);      // 1 pack feeds 4 FFMA2
#pragma unroll
                for (int p = 0; p < 4; p++)
                    ffma2(acc[p][DOFF + d], av, w4r[p]);
            }
        }
    }
}

__global__ void __launch_bounds__(THREADS, 3)
GeneralLinear_841813590622_kernel(const float* __restrict__ x,
                                  const float* __restrict__ w0,
                                  const float* __restrict__ w1,
                                  const float* __restrict__ w2,
                                  float* __restrict__ out)
{
    extern __shared__ float smem[];
    const float* wl[3] = { w0, w1, w2 };

    const int tid = threadIdx.x;
    const int n0 = blockIdx.x * NROWS;
    const int r = tid >> 3, kg = (tid >> 1) & 3, og = tid & 1;

    ull acc[4][9];
#pragma unroll
    for (int p = 0; p < 4; p++)
#pragma unroll
        for (int q = 0; q < 9; q++) acc[p][q] = 0ull;

    // prologue: stage chunks 0 and 1 (both l=0) into slots 0 and 1
    stage_chunk<1>(x, w0, n0, 0, 0, smem,               smem + XS_BUF,               tid);
    asm volatile("cp.async.commit_group;" ::: "memory");
    stage_chunk<1>(x, w0, n0, 1, 0, smem + SLOT_FLOATS, smem + SLOT_FLOATS + XS_BUF, tid);
    asm volatile("cp.async.commit_group;" ::: "memory");

    for (int i = 0; i < 48; i++) {
        // my chunk-i copies landed (chunk i+1's group may stay pending)
        asm volatile("cp.async.wait_group 1;" ::: "memory");
        // everyone's chunk-i copies landed AND compute i-1 is CTA-wide done
        // -> slot (i+2)%3 (chunk i-1's slot) is free for restaging.
        __syncthreads();

        const int nx = i + 2;
        if (nx < 48) {
            const int ln = nx >> 4, cn = nx & 15;
            float* xsn = smem + (size_t)(nx % 3) * SLOT_FLOATS;
            float* wsn = xsn + XS_BUF;
            if (ln == 0)      stage_chunk<1>(x, wl[0], n0, cn, 0,   xsn, wsn, tid);
            else if (ln == 1) stage_chunk<3>(x, wl[1], n0, cn, 64,  xsn, wsn, tid);
            else              stage_chunk<5>(x, wl[2], n0, cn, 256, xsn, wsn, tid);
        }
        asm volatile("cp.async.commit_group;" ::: "memory");

        float* xsb = smem + (size_t)(i % 3) * SLOT_FLOATS;
        float* wsb = xsb + XS_BUF;
        const int l = i >> 4;
        if (l == 0)      compute_chunk<1, 0>(xsb, wsb, acc, r, kg, og);
        else if (l == 1) compute_chunk<3, 1>(xsb, wsb, acc, r, kg, og);
        else             compute_chunk<5, 4>(xsb, wsb, acc, r, kg, og);
    }

    // ---- reduce over kg (lane bits 1..2) via 64-bit butterfly shuffles ----
#pragma unroll
    for (int mask = 2; mask <= 4; mask <<= 1) {
#pragma unroll
        for (int p = 0; p < 4; p++)
#pragma unroll
            for (int q = 0; q < 9; q++) {
                ull o = __shfl_xor_sync(0xffffffffu, acc[p][q], mask);
                acc[p][q] = addf2(acc[p][q], o);
            }
    }

    // ---- kg==0 threads stage their (row, og-half) 72 floats to smem ----
    // slot 0 is safe: chunk 45 (slot 0) was fully consumed before the i=46
    // sync; laggard warps are reading slots 1/2 (chunks 46/47) only.
    const float s = 0.03125f;   // 1/sqrt(1024)
    float* sred = smem;
    if ((tid & 6) == 0) {       // kg == 0
#pragma unroll
        for (int p = 0; p < 4; p++)
#pragma unroll
            for (int q = 0; q < 9; q++) {
                float lo, hi;
                asm("mov.b64 {%0, %1}, %2;" : "=f"(lo), "=f"(hi) : "l"(acc[p][q]));
                sred[r * 144 + (og * 8 + 2 * p) * 9 + q]     = lo * s;
                sred[r * 144 + (og * 8 + 2 * p + 1) * 9 + q] = hi * s;
            }
    }
    __syncthreads();

    // ---- cooperative coalesced float4 store: 16 rows * 144 floats = 576 float4 ----
    const float4* s4 = (const float4*)sred;
    float4* o4 = (float4*)(out + (size_t)n0 * 144);
#pragma unroll
    for (int k = 0; k < 5; k++) {
        int idx = tid + THREADS * k;
        if (idx < 576) o4[idx] = s4[idx];
    }
}

extern "C" void kernel_launch(void* const* d_in, const int* in_sizes, int n_in,
                              void* d_out, int out_size)
{
    const float* x  = (const float*)d_in[0];
    const float* w0 = (const float*)d_in[1];
    const float* w1 = (const float*)d_in[2];
    const float* w2 = (const float*)d_in[3];
    float* out = (float*)d_out;

    cudaFuncSetAttribute(GeneralLinear_841813590622_kernel,
                         cudaFuncAttributeMaxDynamicSharedMemorySize, SMEM_BYTES);
    GeneralLinear_841813590622_kernel<<<512, THREADS, SMEM_BYTES>>>(x, w0, w1, w2, out);
}